// round 2
// baseline (speedup 1.0000x reference)
#include <cuda_runtime.h>

#define NB 4
#define NS 1024
#define ND 256
#define NH 8
#define NDH (ND*NH)   /* 2048 */
#define NM (NB*NS)    /* 4096 */

typedef unsigned long long u64;

// Scratch (device globals: allocation-free per harness rules)
__device__ float g_q[(size_t)NB*NH*NS*ND];
__device__ float g_k[(size_t)NB*NH*NS*ND];
__device__ float g_v[(size_t)NB*NH*NS*ND];
__device__ float g_ao[(size_t)NM*NDH];

// ---- packed f32x2 helpers (sm_103a FFMA2 pipe, PTX-only) ----
__device__ __forceinline__ u64 ffma2(u64 a, u64 b, u64 c){
    u64 d; asm("fma.rn.f32x2 %0, %1, %2, %3;" : "=l"(d) : "l"(a), "l"(b), "l"(c)); return d;
}
__device__ __forceinline__ u64 fmul2(u64 a, u64 b){
    u64 d; asm("mul.rn.f32x2 %0, %1, %2;" : "=l"(d) : "l"(a), "l"(b)); return d;
}
__device__ __forceinline__ u64 dup2(float x){
    u64 r; asm("mov.b64 %0, {%1, %1};" : "=l"(r) : "f"(x)); return r;
}
__device__ __forceinline__ float2 unpk(u64 v){
    float2 f; asm("mov.b64 {%0, %1}, %2;" : "=f"(f.x), "=f"(f.y) : "l"(v)); return f;
}

// ============================================================
// Tiled GEMM: C[M,N] = A[M,K] @ B[K,N] + bias, BM=BN=128, BK=8
// 256 threads, 8x8 micro-tile per thread via FFMA2 (8 rows x 4 f32x2 col-pairs)
// BHSD=true scatters output into [B,H,S,256] layout (QKV projections).
// Ain==nullptr -> read g_ao; Cin==nullptr -> write g_q/g_k/g_v per `which`.
// ============================================================
template<bool BHSD>
__global__ __launch_bounds__(256)
void gemm128(const float* __restrict__ Ain, const float* __restrict__ Bm,
             const float* __restrict__ bias, float* __restrict__ Cin,
             int K, int N, int which)
{
    __shared__ float Ast[8][128];   // A^T tile
    __shared__ float Bs[8][128];
    const float* A = Ain ? Ain : g_ao;
    float* C = Cin ? Cin : (which == 0 ? g_q : which == 1 ? g_k : g_v);

    const int m0 = blockIdx.y * 128, n0 = blockIdx.x * 128;
    const int t  = threadIdx.x;
    const int mx = t & 15, nx = t >> 4;         // C rows: mx+16i, cols: nx*8..nx*8+7
    const int arow = t >> 1,  acol = (t & 1) * 4;   // A tile 128x8 loader
    const int brow = t >> 5,  bcol = (t & 31) * 4;  // B tile 8x128 loader
    const float* Aptr = A  + (size_t)(m0 + arow) * K + acol;
    const float* Bptr = Bm + (size_t)brow * N + n0 + bcol;

    u64 acc[8][4];
    #pragma unroll
    for (int i = 0; i < 8; i++)
        #pragma unroll
        for (int j = 0; j < 4; j++) acc[i][j] = 0ull;

    float4 aF = *(const float4*)Aptr;
    float4 bF = *(const float4*)Bptr;
    const int nk = K >> 3;

    for (int kt = 0; kt < nk; kt++){
        __syncthreads();
        Ast[acol+0][arow] = aF.x; Ast[acol+1][arow] = aF.y;
        Ast[acol+2][arow] = aF.z; Ast[acol+3][arow] = aF.w;
        *(float4*)&Bs[brow][bcol] = bF;
        __syncthreads();
        if (kt + 1 < nk){   // prefetch next tile behind compute
            aF = *(const float4*)(Aptr + (kt + 1) * 8);
            bF = *(const float4*)(Bptr + (size_t)(kt + 1) * 8 * N);
        }
        #pragma unroll
        for (int kk = 0; kk < 8; kk++){
            float a_s[8]; u64 b2[4];
            #pragma unroll
            for (int i = 0; i < 8; i++) a_s[i] = Ast[kk][mx + 16*i];
            #pragma unroll
            for (int jp = 0; jp < 4; jp++) b2[jp] = *(const u64*)&Bs[kk][nx*8 + 2*jp];
            #pragma unroll
            for (int i = 0; i < 8; i++){
                u64 ad = dup2(a_s[i]);
                #pragma unroll
                for (int jp = 0; jp < 4; jp++) acc[i][jp] = ffma2(ad, b2[jp], acc[i][jp]);
            }
        }
    }

    // epilogue: +bias, write
    float2 bb[4];
    #pragma unroll
    for (int jp = 0; jp < 4; jp++) bb[jp] = *(const float2*)&bias[n0 + nx*8 + 2*jp];
    const int n = n0 + nx * 8;
    #pragma unroll
    for (int i = 0; i < 8; i++){
        const int m = m0 + mx + 16*i;
        float2 p0 = unpk(acc[i][0]), p1 = unpk(acc[i][1]);
        float2 p2 = unpk(acc[i][2]), p3 = unpk(acc[i][3]);
        float4 w0 = make_float4(p0.x + bb[0].x, p0.y + bb[0].y, p1.x + bb[1].x, p1.y + bb[1].y);
        float4 w1 = make_float4(p2.x + bb[2].x, p2.y + bb[2].y, p3.x + bb[3].x, p3.y + bb[3].y);
        if (BHSD){
            const int b = m >> 10, s = m & 1023;
            const int h = n >> 8,  e = n & 255;
            float* dst = C + (((size_t)(b*NH + h) * NS + s) << 8) + e;
            *(float4*)dst = w0; *(float4*)(dst + 4) = w1;
        } else {
            float* dst = C + (size_t)m * N + n;
            *(float4*)dst = w0; *(float4*)(dst + 4) = w1;
        }
    }
}

// ============================================================
// Flash attention: one CTA = (b,h) x 64-query block; loops 16 x 64-key blocks.
// Q/K/V fp32 tiles in smem (pad 260 for bank-conflict-free LDS.128),
// online softmax, O accumulators in registers (4 rows x 16 e per thread).
// ============================================================
__global__ __launch_bounds__(256)
void attn64(void)
{
    extern __shared__ float sm[];
    float* Qs   = sm;                    // [64][260]
    float* Ks   = Qs + 64*260;           // [64][260]
    float* Vs   = Ks + 64*260;           // [64][260]
    float* Ps   = Vs + 64*260;           // [64][66]
    float* mrow = Ps + 64*66;            // [64]
    float* lrow = mrow + 64;             // [64]
    float* arow = lrow + 64;             // [64]

    const int bh = blockIdx.y;           // 0..31
    const int qb = blockIdx.x;           // 0..15
    const int t  = threadIdx.x;
    const int tx = t & 15;               // q-row group: rows tx+16i
    const int kx = t >> 4;               // phase1: k-cols kx+16j; phase2: e-block kx*16

    const float* Qg = g_q + ((size_t)bh * NS + qb * 64) * ND;
    const float* Kg = g_k + (size_t)bh * NS * ND;
    const float* Vg = g_v + (size_t)bh * NS * ND;

    // load Q tile (64KB)
    #pragma unroll
    for (int i = 0; i < 16; i++){
        int f = t + 256*i;
        int row = f >> 6, c4 = (f & 63) << 2;
        *(float4*)&Qs[row*260 + c4] = *(const float4*)(Qg + (size_t)row * ND + c4);
    }
    if (t < 64){ mrow[t] = -1e30f; lrow[t] = 0.f; }

    u64 oacc[4][8];
    #pragma unroll
    for (int i = 0; i < 4; i++)
        #pragma unroll
        for (int u = 0; u < 8; u++) oacc[i][u] = 0ull;

    for (int kb = 0; kb < 16; kb++){
        __syncthreads();   // protects Ks/Vs reuse vs previous phase2
        const float* Kgb = Kg + (size_t)kb * 64 * ND;
        const float* Vgb = Vg + (size_t)kb * 64 * ND;
        #pragma unroll
        for (int i = 0; i < 16; i++){
            int f = t + 256*i;
            int row = f >> 6, c4 = (f & 63) << 2;
            *(float4*)&Ks[row*260 + c4] = *(const float4*)(Kgb + (size_t)row * ND + c4);
            *(float4*)&Vs[row*260 + c4] = *(const float4*)(Vgb + (size_t)row * ND + c4);
        }
        __syncthreads();

        // ---- phase 1: S = Q @ K^T (4x4 tile per thread, strided rows) ----
        u64 sac[4][4];
        #pragma unroll
        for (int i = 0; i < 4; i++)
            #pragma unroll
            for (int j = 0; j < 4; j++) sac[i][j] = 0ull;

        #pragma unroll 2
        for (int e = 0; e < 256; e += 4){
            ulonglong2 q4[4], k4[4];
            #pragma unroll
            for (int i = 0; i < 4; i++) q4[i] = *(const ulonglong2*)&Qs[(tx+16*i)*260 + e];
            #pragma unroll
            for (int j = 0; j < 4; j++) k4[j] = *(const ulonglong2*)&Ks[(kx+16*j)*260 + e];
            #pragma unroll
            for (int i = 0; i < 4; i++)
                #pragma unroll
                for (int j = 0; j < 4; j++){
                    sac[i][j] = ffma2(q4[i].x, k4[j].x, sac[i][j]);
                    sac[i][j] = ffma2(q4[i].y, k4[j].y, sac[i][j]);
                }
        }
        #pragma unroll
        for (int i = 0; i < 4; i++)
            #pragma unroll
            for (int j = 0; j < 4; j++){
                float2 p = unpk(sac[i][j]);
                Ps[(tx+16*i)*66 + kx + 16*j] = (p.x + p.y) * 0.0625f;  // / sqrt(256)
            }
        __syncthreads();

        // ---- online softmax (one thread per row) ----
        if (t < 64){
            float mo = mrow[t], mb = mo;
            #pragma unroll
            for (int c = 0; c < 64; c++) mb = fmaxf(mb, Ps[t*66 + c]);
            float al = __expf(mo - mb);
            float ls = 0.f;
            #pragma unroll
            for (int c = 0; c < 64; c++){
                float p = __expf(Ps[t*66 + c] - mb);
                Ps[t*66 + c] = p;
                ls += p;
            }
            lrow[t] = lrow[t] * al + ls;
            mrow[t] = mb;
            arow[t] = al;
        }
        __syncthreads();

        // rescale O accumulators
        u64 ad[4];
        #pragma unroll
        for (int i = 0; i < 4; i++) ad[i] = dup2(arow[tx + 16*i]);
        #pragma unroll
        for (int i = 0; i < 4; i++)
            #pragma unroll
            for (int u = 0; u < 8; u++) oacc[i][u] = fmul2(oacc[i][u], ad[i]);

        // ---- phase 2: O += P @ V (4 rows x 16 e per thread) ----
        #pragma unroll 2
        for (int kk = 0; kk < 64; kk++){
            u64 pd[4];
            #pragma unroll
            for (int i = 0; i < 4; i++) pd[i] = dup2(Ps[(tx+16*i)*66 + kk]);
            ulonglong2 v4[4];
            #pragma unroll
            for (int u = 0; u < 4; u++) v4[u] = *(const ulonglong2*)&Vs[kk*260 + (kx<<4) + 4*u];
            #pragma unroll
            for (int i = 0; i < 4; i++)
                #pragma unroll
                for (int u = 0; u < 4; u++){
                    oacc[i][2*u]   = ffma2(pd[i], v4[u].x, oacc[i][2*u]);
                    oacc[i][2*u+1] = ffma2(pd[i], v4[u].y, oacc[i][2*u+1]);
                }
        }
    }

    // ---- epilogue: O /= l, write [B,S,H*256] ----
    const int b = bh >> 3, h = bh & 7;
    float* outp = g_ao + ((size_t)b * NS + qb * 64) * NDH + h * ND;
    #pragma unroll
    for (int i = 0; i < 4; i++){
        const float linv = 1.0f / lrow[tx + 16*i];
        const int r = tx + 16*i;
        #pragma unroll
        for (int u = 0; u < 4; u++){
            float2 a = unpk(oacc[i][2*u]);
            float2 c = unpk(oacc[i][2*u+1]);
            float4 w = make_float4(a.x*linv, a.y*linv, c.x*linv, c.y*linv);
            *(float4*)(outp + (size_t)r * NDH + (kx<<4) + 4*u) = w;
        }
    }
}

extern "C" void kernel_launch(void* const* d_in, const int* in_sizes, int n_in,
                              void* d_out, int out_size)
{
    const float* Q  = (const float*)d_in[0];
    const float* K  = (const float*)d_in[1];
    const float* V  = (const float*)d_in[2];
    const float* Wq = (const float*)d_in[3];
    const float* bq = (const float*)d_in[4];
    const float* Wk = (const float*)d_in[5];
    const float* bk = (const float*)d_in[6];
    const float* Wv = (const float*)d_in[7];
    const float* bv = (const float*)d_in[8];
    const float* Wo = (const float*)d_in[9];
    const float* bo = (const float*)d_in[10];
    float* out = (float*)d_out;

    const int ATTN_SMEM = (3*64*260 + 64*66 + 3*64) * (int)sizeof(float);  // 217344
    static int attn_attr_set = 0;
    if (!attn_attr_set){
        cudaFuncSetAttribute(attn64, cudaFuncAttributeMaxDynamicSharedMemorySize, ATTN_SMEM);
        attn_attr_set = 1;
    }

    dim3 blk(256);
    dim3 gproj(NDH/128, NM/128);     // (16, 32)
    gemm128<true><<<gproj, blk>>>(Q, Wq, bq, nullptr, ND,  NDH, 0);
    gemm128<true><<<gproj, blk>>>(K, Wk, bk, nullptr, ND,  NDH, 1);
    gemm128<true><<<gproj, blk>>>(V, Wv, bv, nullptr, ND,  NDH, 2);

    dim3 gattn(NS/64, NB*NH);        // (16, 32)
    attn64<<<gattn, blk, ATTN_SMEM>>>();

    dim3 gout(ND/128, NM/128);       // (2, 32)
    gemm128<false><<<gout, blk>>>(nullptr, Wo, bo, out, NDH, ND, 0);
}

// round 5
// speedup vs baseline: 1.5659x; 1.5659x over previous
#include <cuda_runtime.h>
#include <cuda_bf16.h>

typedef unsigned int u32;

#define NS 1024
#define ND 256
#define NH 8
#define NDH 2048
#define NM 4096
#define HEADS 32
#define HEL ((size_t)NS*ND)

// ---------------- device scratch ----------------
__device__ __nv_bfloat16 g_xh[3][(size_t)NM*ND],  g_xl[3][(size_t)NM*ND];
__device__ __nv_bfloat16 g_wth[3][(size_t)NDH*ND], g_wtl[3][(size_t)NDH*ND];
__device__ __nv_bfloat16 g_woth[(size_t)ND*NDH],  g_wotl[(size_t)ND*NDH];
__device__ __nv_bfloat16 g_qh[HEADS*HEL], g_ql[HEADS*HEL];
__device__ __nv_bfloat16 g_kh[HEADS*HEL], g_kl[HEADS*HEL];
__device__ __nv_bfloat16 g_vth[HEADS*HEL], g_vtl[HEADS*HEL];   // [b,h,e,s]
__device__ __nv_bfloat16 g_aoh[(size_t)NM*NDH], g_aol[(size_t)NM*NDH];

// ---------------- helpers ----------------
__device__ __forceinline__ u32 smem_u32(const void* p){
    u32 a; asm("{ .reg .u64 t; cvta.to.shared.u64 t, %1; cvt.u32.u64 %0, t; }" : "=r"(a) : "l"(p));
    return a;
}
__device__ __forceinline__ void split2(float v, __nv_bfloat16& h, __nv_bfloat16& l){
    h = __float2bfloat16_rn(v);
    l = __float2bfloat16_rn(v - __bfloat162float(h));
}
#define LDMX4(r, a) \
    asm volatile("ldmatrix.sync.aligned.m8n8.x4.shared.b16 {%0,%1,%2,%3}, [%4];" \
        : "=r"((r)[0]),"=r"((r)[1]),"=r"((r)[2]),"=r"((r)[3]) : "r"(a))
#define MMA(c, a, b0, b1) \
    asm volatile("mma.sync.aligned.m16n8k16.row.col.f32.bf16.bf16.f32 " \
        "{%0,%1,%2,%3}, {%4,%5,%6,%7}, {%8,%9}, {%0,%1,%2,%3};" \
        : "+f"((c)[0]),"+f"((c)[1]),"+f"((c)[2]),"+f"((c)[3]) \
        : "r"((a)[0]),"r"((a)[1]),"r"((a)[2]),"r"((a)[3]), "r"(b0),"r"(b1))

// ---------------- prep: fp32 -> bf16 hi/lo split ----------------
__global__ __launch_bounds__(256)
void splitk(const float* __restrict__ a, int sel, int n)
{
    int i = (blockIdx.x*256 + threadIdx.x)*4;
    if (i >= n) return;
    __nv_bfloat16* h = g_xh[sel];
    __nv_bfloat16* l = g_xl[sel];
    float4 v = *(const float4*)(a + i);
    __nv_bfloat16 h0,l0,h1,l1,h2,l2,h3,l3;
    split2(v.x,h0,l0); split2(v.y,h1,l1); split2(v.z,h2,l2); split2(v.w,h3,l3);
    *(__nv_bfloat162*)(h+i)   = __halves2bfloat162(h0,h1);
    *(__nv_bfloat162*)(h+i+2) = __halves2bfloat162(h2,h3);
    *(__nv_bfloat162*)(l+i)   = __halves2bfloat162(l0,l1);
    *(__nv_bfloat162*)(l+i+2) = __halves2bfloat162(l2,l3);
}

// transpose W[R][C] -> out[C][R] with hi/lo split. sel 0..2 -> g_wth[sel]; 3 -> g_woth
__global__ __launch_bounds__(256)
void wtrans(const float* __restrict__ W, int R, int C, int sel)
{
    __shared__ float tile[32][33];
    const int c0 = blockIdx.x*32, r0 = blockIdx.y*32;
    const int tx = threadIdx.x & 31, ty = threadIdx.x >> 5;
    __nv_bfloat16* th = (sel < 3) ? g_wth[sel] : g_woth;
    __nv_bfloat16* tl = (sel < 3) ? g_wtl[sel] : g_wotl;
    #pragma unroll
    for (int i = 0; i < 4; i++)
        tile[ty + 8*i][tx] = W[(size_t)(r0 + ty + 8*i)*C + c0 + tx];
    __syncthreads();
    #pragma unroll
    for (int i = 0; i < 4; i++){
        float v = tile[tx][ty + 8*i];
        __nv_bfloat16 h, l; split2(v, h, l);
        size_t d = (size_t)(c0 + ty + 8*i)*R + r0 + tx;
        th[d] = h; tl[d] = l;
    }
}

// ============================================================
// proj: C[4096,N] = A[4096,K] @ Bt^T + bias, bf16x3 via mma.sync
// MODE 0: scatter bf16 hi/lo -> g_qh/ql (wsel 0) or g_kh/kl (wsel 1)
// MODE 1: scatter bf16 hi/lo transposed -> g_vth/vtl [b,h,e,s]
// MODE 2: fp32 row-major -> fout [4096][256]
// asel: 0..2 -> g_xh[asel]; -1 -> g_aoh. bsel: 0..2 -> g_wth; -1 -> g_woth.
// tile 128x128, 8 warps (2m x 4n), warp tile 64x32, K chunks of 64.
// ============================================================
template<int MODE>
__global__ __launch_bounds__(256)
void proj(int asel, int bsel, const float* __restrict__ bias, float* __restrict__ fout,
          int Kd, int wsel)
{
    extern __shared__ char sm[];     // sAh 0, sAl 18432, sBh 36864, sBl 55296 (stride 72 bf16)
    const u32 sb = smem_u32(sm);
    const __nv_bfloat16* Ah = (asel < 0) ? g_aoh : g_xh[asel];
    const __nv_bfloat16* Al = (asel < 0) ? g_aol : g_xl[asel];
    const __nv_bfloat16* Bh = (bsel < 0) ? g_woth : g_wth[bsel];
    const __nv_bfloat16* Bl = (bsel < 0) ? g_wotl : g_wtl[bsel];

    const int t = threadIdx.x, wid = t >> 5, lane = t & 31;
    const int g = lane >> 2, tg = lane & 3;
    const int m0 = blockIdx.y*128, n0 = blockIdx.x*128;
    const int wm = wid >> 2, wn = wid & 3;

    float acc[4][4][4];
    #pragma unroll
    for (int a = 0; a < 4; a++)
        #pragma unroll
        for (int b = 0; b < 4; b++)
            #pragma unroll
            for (int c = 0; c < 4; c++) acc[a][b][c] = 0.f;

    for (int c = 0; c < (Kd >> 6); c++){
        __syncthreads();
        #pragma unroll
        for (int i = 0; i < 4; i++){
            int idx = t + 256*i;
            int row = idx >> 3, c8 = (idx & 7)*8;
            u32 so = (u32)(row*72 + c8)*2;
            size_t ga = (size_t)(m0 + row)*Kd + c*64 + c8;
            size_t gb = (size_t)(n0 + row)*Kd + c*64 + c8;
            *(uint4*)(sm + so)         = *(const uint4*)(Ah + ga);
            *(uint4*)(sm + 18432 + so) = *(const uint4*)(Al + ga);
            *(uint4*)(sm + 36864 + so) = *(const uint4*)(Bh + gb);
            *(uint4*)(sm + 55296 + so) = *(const uint4*)(Bl + gb);
        }
        __syncthreads();
        #pragma unroll
        for (int ks = 0; ks < 4; ks++){
            u32 ah[4][4], al[4][4], bh[2][4], bl[2][4];
            #pragma unroll
            for (int mt = 0; mt < 4; mt++){
                u32 off = (u32)((64*wm + 16*mt + (lane & 15))*72 + ks*16 + 8*(lane >> 4))*2;
                LDMX4(ah[mt], sb + off);
                LDMX4(al[mt], sb + 18432 + off);
            }
            #pragma unroll
            for (int p = 0; p < 2; p++){
                u32 off = (u32)((32*wn + 16*p + 8*(lane >> 4) + (lane & 7))*72
                                + ks*16 + 8*((lane >> 3) & 1))*2;
                LDMX4(bh[p], sb + 36864 + off);
                LDMX4(bl[p], sb + 55296 + off);
            }
            #pragma unroll
            for (int mt = 0; mt < 4; mt++)
                #pragma unroll
                for (int nt = 0; nt < 4; nt++){
                    const u32* ph = &bh[nt >> 1][(nt & 1)*2];
                    const u32* pl = &bl[nt >> 1][(nt & 1)*2];
                    MMA(acc[mt][nt], ah[mt], ph[0], ph[1]);
                    MMA(acc[mt][nt], ah[mt], pl[0], pl[1]);
                    MMA(acc[mt][nt], al[mt], ph[0], ph[1]);
                }
        }
    }

    __nv_bfloat16* OH = wsel ? g_kh : g_qh;
    __nv_bfloat16* OL = wsel ? g_kl : g_ql;
    #pragma unroll
    for (int mt = 0; mt < 4; mt++)
        #pragma unroll
        for (int nt = 0; nt < 4; nt++)
            #pragma unroll
            for (int hf = 0; hf < 2; hf++){
                int row = m0 + 64*wm + 16*mt + g + 8*hf;
                int col = n0 + 32*wn + 8*nt + 2*tg;
                float v0 = acc[mt][nt][2*hf]   + bias[col];
                float v1 = acc[mt][nt][2*hf+1] + bias[col+1];
                if (MODE == 2){
                    float2 w = make_float2(v0, v1);
                    *(float2*)(fout + (size_t)row*ND + col) = w;
                } else {
                    int b = row >> 10, s = row & 1023, h = col >> 8, e = col & 255;
                    __nv_bfloat16 h0,l0,h1,l1; split2(v0,h0,l0); split2(v1,h1,l1);
                    if (MODE == 0){
                        size_t d = ((size_t)(b*NH + h)*NS + s)*ND + e;
                        *(__nv_bfloat162*)(OH + d) = __halves2bfloat162(h0,h1);
                        *(__nv_bfloat162*)(OL + d) = __halves2bfloat162(l0,l1);
                    } else {
                        size_t d = ((size_t)(b*NH + h)*ND + e)*NS + s;
                        g_vth[d] = h0; g_vtl[d] = l0;
                        g_vth[d + NS] = h1; g_vtl[d + NS] = l1;
                    }
                }
            }
}

// ============================================================
// attn: CTA = (b,h) x 64 queries; 16 key blocks of 64.
// S fragments in regs -> exp (no max shift) -> P hi/lo smem -> O frags
// accumulate un-normalized across blocks; divide by rowsum at end.
// smem: QH 0 (33792) QL 33792 | KVH 67584 (36864) KVL 104448 | PH 141312 (9216) PL 150528 | lsum 159744
// ============================================================
__global__ __launch_bounds__(256)
void attn()
{
    extern __shared__ char sm[];
    const u32 sb = smem_u32(sm);
    const int t = threadIdx.x, wid = t >> 5, lane = t & 31;
    const int g = lane >> 2, tg = lane & 3;
    const int qb = blockIdx.x, bh = blockIdx.y;
    const int wm = wid >> 1, wn = wid & 1;       // 4x2 warp grid for both phases
    float* lsum = (float*)(sm + 159744);

    const size_t ho = (size_t)bh * HEL;
    const __nv_bfloat16* qh = g_qh + ho + (size_t)qb*64*ND;
    const __nv_bfloat16* ql = g_ql + ho + (size_t)qb*64*ND;
    const __nv_bfloat16* kh = g_kh + ho;
    const __nv_bfloat16* kl = g_kl + ho;
    const __nv_bfloat16* vth = g_vth + ho;
    const __nv_bfloat16* vtl = g_vtl + ho;

    #pragma unroll
    for (int i = 0; i < 8; i++){          // Q tile [64][264 stride]
        int idx = t + 256*i;
        int row = idx >> 5, c8 = (idx & 31)*8;
        u32 so = (u32)(row*264 + c8)*2;
        *(uint4*)(sm + so)         = *(const uint4*)(qh + (size_t)row*ND + c8);
        *(uint4*)(sm + 33792 + so) = *(const uint4*)(ql + (size_t)row*ND + c8);
    }
    if (t < 64) lsum[t] = 0.f;

    float oacc[16][4];
    #pragma unroll
    for (int a = 0; a < 16; a++)
        #pragma unroll
        for (int c = 0; c < 4; c++) oacc[a][c] = 0.f;
    __syncthreads();

    for (int kb = 0; kb < 16; kb++){
        #pragma unroll
        for (int i = 0; i < 8; i++){      // K block [64][264]
            int idx = t + 256*i;
            int row = idx >> 5, c8 = (idx & 31)*8;
            u32 so = (u32)(row*264 + c8)*2;
            size_t ga = (size_t)(kb*64 + row)*ND + c8;
            *(uint4*)(sm + 67584 + so)  = *(const uint4*)(kh + ga);
            *(uint4*)(sm + 104448 + so) = *(const uint4*)(kl + ga);
        }
        __syncthreads();

        // phase 1: S[16 rows][32 cols] per warp
        float sacc[4][4];
        #pragma unroll
        for (int a = 0; a < 4; a++)
            #pragma unroll
            for (int c = 0; c < 4; c++) sacc[a][c] = 0.f;
        #pragma unroll
        for (int ks = 0; ks < 16; ks++){
            u32 a_h[4], a_l[4], b_h[2][4], b_l[2][4];
            u32 offA = (u32)((16*wm + (lane & 15))*264 + ks*16 + 8*(lane >> 4))*2;
            LDMX4(a_h, sb + offA);
            LDMX4(a_l, sb + 33792 + offA);
            #pragma unroll
            for (int p = 0; p < 2; p++){
                u32 offB = (u32)((32*wn + 16*p + 8*(lane >> 4) + (lane & 7))*264
                                 + ks*16 + 8*((lane >> 3) & 1))*2;
                LDMX4(b_h[p], sb + 67584 + offB);
                LDMX4(b_l[p], sb + 104448 + offB);
            }
            #pragma unroll
            for (int nt = 0; nt < 4; nt++){
                const u32* ph = &b_h[nt >> 1][(nt & 1)*2];
                const u32* pl = &b_l[nt >> 1][(nt & 1)*2];
                MMA(sacc[nt], a_h, ph[0], ph[1]);
                MMA(sacc[nt], a_h, pl[0], pl[1]);
                MMA(sacc[nt], a_l, ph[0], ph[1]);
            }
        }

        // softmax (no shift) + P store
        float ls0 = 0.f, ls1 = 0.f;
        #pragma unroll
        for (int nt = 0; nt < 4; nt++){
            float p0 = __expf(sacc[nt][0]*0.0625f);
            float p1 = __expf(sacc[nt][1]*0.0625f);
            float p2 = __expf(sacc[nt][2]*0.0625f);
            float p3 = __expf(sacc[nt][3]*0.0625f);
            ls0 += p0 + p1; ls1 += p2 + p3;
            int col = 32*wn + 8*nt + 2*tg;
            int r0 = 16*wm + g;
            __nv_bfloat16 h0,l0,h1,l1,h2,l2,h3,l3;
            split2(p0,h0,l0); split2(p1,h1,l1); split2(p2,h2,l2); split2(p3,h3,l3);
            u32 o0 = (u32)(r0*72 + col)*2, o1 = (u32)((r0+8)*72 + col)*2;
            *(__nv_bfloat162*)(sm + 141312 + o0) = __halves2bfloat162(h0,h1);
            *(__nv_bfloat162*)(sm + 150528 + o0) = __halves2bfloat162(l0,l1);
            *(__nv_bfloat162*)(sm + 141312 + o1) = __halves2bfloat162(h2,h3);
            *(__nv_bfloat162*)(sm + 150528 + o1) = __halves2bfloat162(l2,l3);
        }
        ls0 += __shfl_xor_sync(0xFFFFFFFFu, ls0, 1);
        ls0 += __shfl_xor_sync(0xFFFFFFFFu, ls0, 2);
        ls1 += __shfl_xor_sync(0xFFFFFFFFu, ls1, 1);
        ls1 += __shfl_xor_sync(0xFFFFFFFFu, ls1, 2);
        if (tg == 0){
            atomicAdd(&lsum[16*wm + g], ls0);
            atomicAdd(&lsum[16*wm + g + 8], ls1);
        }
        __syncthreads();   // K reads + P writes complete

        #pragma unroll
        for (int i = 0; i < 8; i++){      // V^T block [256][72 stride]
            int idx = t + 256*i;
            int row = idx >> 3, c8 = (idx & 7)*8;
            u32 so = (u32)(row*72 + c8)*2;
            size_t ga = (size_t)row*NS + kb*64 + c8;
            *(uint4*)(sm + 67584 + so)  = *(const uint4*)(vth + ga);
            *(uint4*)(sm + 104448 + so) = *(const uint4*)(vtl + ga);
        }
        __syncthreads();

        // phase 2: O[16 rows][128 cols] per warp, k=64
        #pragma unroll
        for (int ks = 0; ks < 4; ks++){
            u32 a_h[4], a_l[4];
            u32 offA = (u32)((16*wm + (lane & 15))*72 + ks*16 + 8*(lane >> 4))*2;
            LDMX4(a_h, sb + 141312 + offA);
            LDMX4(a_l, sb + 150528 + offA);
            #pragma unroll
            for (int p = 0; p < 8; p++){
                u32 b_h[4], b_l[4];
                u32 offB = (u32)((128*wn + 16*p + 8*(lane >> 4) + (lane & 7))*72
                                 + ks*16 + 8*((lane >> 3) & 1))*2;
                LDMX4(b_h, sb + 67584 + offB);
                LDMX4(b_l, sb + 104448 + offB);
                MMA(oacc[2*p],   a_h, b_h[0], b_h[1]);
                MMA(oacc[2*p],   a_h, b_l[0], b_l[1]);
                MMA(oacc[2*p],   a_l, b_h[0], b_h[1]);
                MMA(oacc[2*p+1], a_h, b_h[2], b_h[3]);
                MMA(oacc[2*p+1], a_h, b_l[2], b_l[3]);
                MMA(oacc[2*p+1], a_l, b_h[2], b_h[3]);
            }
        }
        __syncthreads();   // V reads done before next K overwrite
    }

    const int r0 = 16*wm + g, r1 = r0 + 8;
    const float li0 = 1.0f / lsum[r0], li1 = 1.0f / lsum[r1];
    const int b = bh >> 3, h = bh & 7;
    const size_t gr0 = (size_t)(b*NS + qb*64 + r0)*NDH + (size_t)h*ND;
    const size_t gr1 = (size_t)(b*NS + qb*64 + r1)*NDH + (size_t)h*ND;
    #pragma unroll
    for (int nt = 0; nt < 16; nt++){
        int e = 128*wn + 8*nt + 2*tg;
        __nv_bfloat16 h0,l0,h1,l1,h2,l2,h3,l3;
        split2(oacc[nt][0]*li0, h0,l0); split2(oacc[nt][1]*li0, h1,l1);
        split2(oacc[nt][2]*li1, h2,l2); split2(oacc[nt][3]*li1, h3,l3);
        *(__nv_bfloat162*)(g_aoh + gr0 + e) = __halves2bfloat162(h0,h1);
        *(__nv_bfloat162*)(g_aol + gr0 + e) = __halves2bfloat162(l0,l1);
        *(__nv_bfloat162*)(g_aoh + gr1 + e) = __halves2bfloat162(h2,h3);
        *(__nv_bfloat162*)(g_aol + gr1 + e) = __halves2bfloat162(l2,l3);
    }
}

extern "C" void kernel_launch(void* const* d_in, const int* in_sizes, int n_in,
                              void* d_out, int out_size)
{
    const float* Q  = (const float*)d_in[0];
    const float* K  = (const float*)d_in[1];
    const float* V  = (const float*)d_in[2];
    const float* Wq = (const float*)d_in[3];
    const float* bq = (const float*)d_in[4];
    const float* Wk = (const float*)d_in[5];
    const float* bk = (const float*)d_in[6];
    const float* Wv = (const float*)d_in[7];
    const float* bv = (const float*)d_in[8];
    const float* Wo = (const float*)d_in[9];
    const float* bo = (const float*)d_in[10];
    float* out = (float*)d_out;

    const int PROJ_SMEM = 73728;
    const int ATTN_SMEM = 160000;
    cudaFuncSetAttribute(proj<0>, cudaFuncAttributeMaxDynamicSharedMemorySize, PROJ_SMEM);
    cudaFuncSetAttribute(proj<1>, cudaFuncAttributeMaxDynamicSharedMemorySize, PROJ_SMEM);
    cudaFuncSetAttribute(proj<2>, cudaFuncAttributeMaxDynamicSharedMemorySize, PROJ_SMEM);
    cudaFuncSetAttribute(attn,    cudaFuncAttributeMaxDynamicSharedMemorySize, ATTN_SMEM);

    dim3 blk(256);
    splitk<<<1024, blk>>>(Q, 0, NM*ND);
    splitk<<<1024, blk>>>(K, 1, NM*ND);
    splitk<<<1024, blk>>>(V, 2, NM*ND);
    wtrans<<<dim3(64, 8), blk>>>(Wq, ND, NDH, 0);
    wtrans<<<dim3(64, 8), blk>>>(Wk, ND, NDH, 1);
    wtrans<<<dim3(64, 8), blk>>>(Wv, ND, NDH, 2);
    wtrans<<<dim3(8, 64), blk>>>(Wo, NDH, ND, 3);

    proj<0><<<dim3(16, 32), blk, PROJ_SMEM>>>(0, 0, bq, nullptr, ND, 0);
    proj<0><<<dim3(16, 32), blk, PROJ_SMEM>>>(1, 1, bk, nullptr, ND, 1);
    proj<1><<<dim3(16, 32), blk, PROJ_SMEM>>>(2, 2, bv, nullptr, ND, 0);

    attn<<<dim3(16, 32), blk, ATTN_SMEM>>>();

    proj<2><<<dim3(2, 32), blk, PROJ_SMEM>>>(-1, -1, bo, out, NDH, 0);
}

// round 7
// speedup vs baseline: 2.2205x; 1.4180x over previous
#include <cuda_runtime.h>
#include <cuda_bf16.h>

typedef unsigned int u32;

#define NS 1024
#define ND 256
#define NH 8
#define NDH 2048
#define NM 4096
#define HEADS 32
#define HEL ((size_t)NS*ND)

// ---------------- device scratch ----------------
__device__ __nv_bfloat16 g_xh[3][(size_t)NM*ND],  g_xl[3][(size_t)NM*ND];
__device__ __nv_bfloat16 g_wth[3][(size_t)NDH*ND], g_wtl[3][(size_t)NDH*ND];
__device__ __nv_bfloat16 g_woth[(size_t)ND*NDH],  g_wotl[(size_t)ND*NDH];
__device__ __nv_bfloat16 g_qh[HEADS*HEL], g_ql[HEADS*HEL];
__device__ __nv_bfloat16 g_kh[HEADS*HEL], g_kl[HEADS*HEL];
__device__ __nv_bfloat16 g_vth[HEADS*HEL], g_vtl[HEADS*HEL];   // [b,h,e,s]
__device__ __nv_bfloat16 g_aoh[(size_t)NM*NDH], g_aol[(size_t)NM*NDH];

// ---------------- helpers ----------------
__device__ __forceinline__ u32 smem_u32(const void* p){
    u32 a; asm("{ .reg .u64 t; cvta.to.shared.u64 t, %1; cvt.u32.u64 %0, t; }" : "=r"(a) : "l"(p));
    return a;
}
__device__ __forceinline__ void split2(float v, __nv_bfloat16& h, __nv_bfloat16& l){
    h = __float2bfloat16_rn(v);
    l = __float2bfloat16_rn(v - __bfloat162float(h));
}
#define LDMX4(r, a) \
    asm volatile("ldmatrix.sync.aligned.m8n8.x4.shared.b16 {%0,%1,%2,%3}, [%4];" \
        : "=r"((r)[0]),"=r"((r)[1]),"=r"((r)[2]),"=r"((r)[3]) : "r"(a))
#define MMA(c, a, b0, b1) \
    asm volatile("mma.sync.aligned.m16n8k16.row.col.f32.bf16.bf16.f32 " \
        "{%0,%1,%2,%3}, {%4,%5,%6,%7}, {%8,%9}, {%0,%1,%2,%3};" \
        : "+f"((c)[0]),"+f"((c)[1]),"+f"((c)[2]),"+f"((c)[3]) \
        : "r"((a)[0]),"r"((a)[1]),"r"((a)[2]),"r"((a)[3]), "r"(b0),"r"(b1))
#define CPA16(dst, src) \
    asm volatile("cp.async.cg.shared.global [%0], [%1], 16;" :: "r"(dst), "l"(src))
#define CPA_COMMIT() asm volatile("cp.async.commit_group;")
#define CPA_WAIT(n)  asm volatile("cp.async.wait_group %0;" :: "n"(n))

// ---------------- fused prep ----------------
__global__ __launch_bounds__(256)
void splitall(const float* __restrict__ Q, const float* __restrict__ K,
              const float* __restrict__ V)
{
    const int sel = blockIdx.y;
    const float* a = (sel == 0) ? Q : (sel == 1) ? K : V;
    int i = (blockIdx.x*256 + threadIdx.x)*4;
    __nv_bfloat16* h = g_xh[sel];
    __nv_bfloat16* l = g_xl[sel];
    float4 v = *(const float4*)(a + i);
    __nv_bfloat16 h0,l0,h1,l1,h2,l2,h3,l3;
    split2(v.x,h0,l0); split2(v.y,h1,l1); split2(v.z,h2,l2); split2(v.w,h3,l3);
    *(__nv_bfloat162*)(h+i)   = __halves2bfloat162(h0,h1);
    *(__nv_bfloat162*)(h+i+2) = __halves2bfloat162(h2,h3);
    *(__nv_bfloat162*)(l+i)   = __halves2bfloat162(l0,l1);
    *(__nv_bfloat162*)(l+i+2) = __halves2bfloat162(l2,l3);
}

__global__ __launch_bounds__(256)
void wtransall(const float* __restrict__ Wq, const float* __restrict__ Wk,
               const float* __restrict__ Wv, const float* __restrict__ Wo)
{
    __shared__ float tile[32][33];
    const int z = blockIdx.z;
    const float* W = (z==0) ? Wq : (z==1) ? Wk : (z==2) ? Wv : Wo;
    const int R = (z<3) ? ND : NDH, C = (z<3) ? NDH : ND;
    const int c0 = ((z<3) ? blockIdx.x : blockIdx.y)*32;
    const int r0 = ((z<3) ? blockIdx.y : blockIdx.x)*32;
    const int tx = threadIdx.x & 31, ty = threadIdx.x >> 5;
    __nv_bfloat16* th = (z<3) ? g_wth[z] : g_woth;
    __nv_bfloat16* tl = (z<3) ? g_wtl[z] : g_wotl;
    #pragma unroll
    for (int i = 0; i < 4; i++)
        tile[ty + 8*i][tx] = W[(size_t)(r0 + ty + 8*i)*C + c0 + tx];
    __syncthreads();
    #pragma unroll
    for (int i = 0; i < 4; i++){
        float v = tile[tx][ty + 8*i];
        __nv_bfloat16 h, l; split2(v, h, l);
        size_t d = (size_t)(c0 + ty + 8*i)*R + r0 + tx;
        th[d] = h; tl[d] = l;
    }
}

// ============================================================
// proj: C[4096,N] = A[4096,K] @ Bt^T + bias, bf16x3, cp.async double-buffer
// MODE 0: Q/K scatter; MODE 1: V scatter transposed
// ============================================================
template<int MODE>
__global__ __launch_bounds__(256)
void proj(int asel, int bsel, const float* __restrict__ bias,
          int Kd, int wsel)
{
    extern __shared__ char sm[];   // per buf 73728: Ah 0, Al 18432, Bh 36864, Bl 55296 (stride 72)
    const u32 sb = smem_u32(sm);
    const __nv_bfloat16* Ah = g_xh[asel];
    const __nv_bfloat16* Al = g_xl[asel];
    const __nv_bfloat16* Bh = g_wth[bsel];
    const __nv_bfloat16* Bl = g_wtl[bsel];

    const int t = threadIdx.x, wid = t >> 5, lane = t & 31;
    const int g = lane >> 2, tg = lane & 3;
    const int m0 = blockIdx.y*128, n0 = blockIdx.x*128;
    const int wm = wid >> 2, wn = wid & 3;
    const int nc = Kd >> 6;

    float acc[4][4][4];
    #pragma unroll
    for (int a = 0; a < 4; a++)
        #pragma unroll
        for (int b = 0; b < 4; b++)
            #pragma unroll
            for (int c = 0; c < 4; c++) acc[a][b][c] = 0.f;

    const int lrow = t >> 3, lc8 = (t & 7)*8;       // loader: 32 rows per pass
    {
        #pragma unroll
        for (int i = 0; i < 4; i++){
            int row = lrow + 32*i;
            u32 so = (u32)(row*72 + lc8)*2;
            size_t ga = (size_t)(m0 + row)*Kd + lc8;
            size_t gb = (size_t)(n0 + row)*Kd + lc8;
            CPA16(sb + so,         (const char*)(Ah + ga));
            CPA16(sb + 18432 + so, (const char*)(Al + ga));
            CPA16(sb + 36864 + so, (const char*)(Bh + gb));
            CPA16(sb + 55296 + so, (const char*)(Bl + gb));
        }
        CPA_COMMIT();
    }

    for (int c = 0; c < nc; c++){
        if (c + 1 < nc){
            u32 nb = (u32)((c+1) & 1)*73728u;
            #pragma unroll
            for (int i = 0; i < 4; i++){
                int row = lrow + 32*i;
                u32 so = nb + (u32)(row*72 + lc8)*2;
                size_t ga = (size_t)(m0 + row)*Kd + (c+1)*64 + lc8;
                size_t gb = (size_t)(n0 + row)*Kd + (c+1)*64 + lc8;
                CPA16(sb + so,         (const char*)(Ah + ga));
                CPA16(sb + 18432 + so, (const char*)(Al + ga));
                CPA16(sb + 36864 + so, (const char*)(Bh + gb));
                CPA16(sb + 55296 + so, (const char*)(Bl + gb));
            }
            CPA_COMMIT();
            CPA_WAIT(1);
        } else {
            CPA_WAIT(0);
        }
        __syncthreads();
        const u32 cb = (u32)(c & 1)*73728u;
        #pragma unroll
        for (int ks = 0; ks < 4; ks++){
            u32 ah[4][4], al[4][4], bh[2][4], bl[2][4];
            #pragma unroll
            for (int mt = 0; mt < 4; mt++){
                u32 off = cb + (u32)((64*wm + 16*mt + (lane & 15))*72 + ks*16 + 8*(lane >> 4))*2;
                LDMX4(ah[mt], sb + off);
                LDMX4(al[mt], sb + 18432 + off);
            }
            #pragma unroll
            for (int p = 0; p < 2; p++){
                u32 off = cb + (u32)((32*wn + 16*p + 8*(lane >> 4) + (lane & 7))*72
                                + ks*16 + 8*((lane >> 3) & 1))*2;
                LDMX4(bh[p], sb + 36864 + off);
                LDMX4(bl[p], sb + 55296 + off);
            }
            #pragma unroll
            for (int mt = 0; mt < 4; mt++)
                #pragma unroll
                for (int nt = 0; nt < 4; nt++){
                    const u32* ph = &bh[nt >> 1][(nt & 1)*2];
                    const u32* pl = &bl[nt >> 1][(nt & 1)*2];
                    MMA(acc[mt][nt], ah[mt], ph[0], ph[1]);
                    MMA(acc[mt][nt], ah[mt], pl[0], pl[1]);
                    MMA(acc[mt][nt], al[mt], ph[0], ph[1]);
                }
        }
        __syncthreads();
    }

    __nv_bfloat16* OH = wsel ? g_kh : g_qh;
    __nv_bfloat16* OL = wsel ? g_kl : g_ql;
    #pragma unroll
    for (int mt = 0; mt < 4; mt++)
        #pragma unroll
        for (int nt = 0; nt < 4; nt++)
            #pragma unroll
            for (int hf = 0; hf < 2; hf++){
                int row = m0 + 64*wm + 16*mt + g + 8*hf;
                int col = n0 + 32*wn + 8*nt + 2*tg;
                float v0 = acc[mt][nt][2*hf]   + bias[col];
                float v1 = acc[mt][nt][2*hf+1] + bias[col+1];
                int b = row >> 10, s = row & 1023, h = col >> 8, e = col & 255;
                __nv_bfloat16 h0,l0,h1,l1; split2(v0,h0,l0); split2(v1,h1,l1);
                if (MODE == 0){
                    size_t d = ((size_t)(b*NH + h)*NS + s)*ND + e;
                    *(__nv_bfloat162*)(OH + d) = __halves2bfloat162(h0,h1);
                    *(__nv_bfloat162*)(OL + d) = __halves2bfloat162(l0,l1);
                } else {
                    size_t d = ((size_t)(b*NH + h)*ND + e)*NS + s;
                    g_vth[d] = h0; g_vtl[d] = l0;
                    g_vth[d + NS] = h1; g_vtl[d + NS] = l1;
                }
            }
}

// ============================================================
// attn: CTA = (b,h) x 64 queries; 16 key blocks of 64; swizzled smem;
// cp.async pipelining: V_kb loads under phase1, K_{kb+1} under phase2.
// smem: QH 0 QL 32768 | KH 65536 KL 98304 | VH 131072 VL 163840 |
//       PH 196608 PL 204800 | lsum 212992 (2x64 f32)
// ============================================================
__global__ __launch_bounds__(256)
void attn()
{
    extern __shared__ char sm[];
    const u32 sb = smem_u32(sm);
    const int t = threadIdx.x, wid = t >> 5, lane = t & 31;
    const int g = lane >> 2, tg = lane & 3;
    const int qb = blockIdx.x, bh = blockIdx.y;
    const int wm = wid >> 1, wn = wid & 1;
    float* lsum = (float*)(sm + 212992);

    const size_t ho = (size_t)bh * HEL;
    const __nv_bfloat16* qh = g_qh + ho + (size_t)qb*64*ND;
    const __nv_bfloat16* ql = g_ql + ho + (size_t)qb*64*ND;
    const __nv_bfloat16* kh = g_kh + ho;
    const __nv_bfloat16* kl = g_kl + ho;
    const __nv_bfloat16* vth = g_vth + ho;
    const __nv_bfloat16* vtl = g_vtl + ho;

    // K loader geometry: 64 rows, 4 threads/row, 8 chunks (8 bf16) each = full [64][256]
    const int krow = t >> 2, kcb = (t & 3)*64;

    // issue K block 0 via cp.async (group 0)
    #pragma unroll
    for (int cc = 0; cc < 8; cc++){
        int col = kcb + cc*8;
        u32 so = (u32)krow*512 + (u32)(((col>>3) ^ (krow&7))<<4);
        size_t ga = (size_t)krow*ND + col;
        CPA16(sb + 65536 + so, (const char*)(kh + ga));
        CPA16(sb + 98304 + so, (const char*)(kl + ga));
    }
    CPA_COMMIT();

    // Q tile (plain loads, swizzled)
    #pragma unroll
    for (int i = 0; i < 8; i++){
        int idx = t + 256*i;
        int row = idx >> 5, c8 = (idx & 31)*8;
        u32 so = (u32)row*512 + (u32)(((c8>>3) ^ (row&7))<<4);
        *(uint4*)(sm + so)         = *(const uint4*)(qh + (size_t)row*ND + c8);
        *(uint4*)(sm + 32768 + so) = *(const uint4*)(ql + (size_t)row*ND + c8);
    }

    float oacc[16][4];
    #pragma unroll
    for (int a = 0; a < 16; a++)
        #pragma unroll
        for (int c = 0; c < 4; c++) oacc[a][c] = 0.f;
    float lacc0 = 0.f, lacc1 = 0.f;

    for (int kb = 0; kb < 16; kb++){
        // issue V_kb (overlaps phase1): [256 e][64 s], 8 chunks per row
        #pragma unroll
        for (int cc = 0; cc < 8; cc++){
            int col = cc*8;
            u32 so = (u32)t*128 + (u32)((cc ^ (t&7))<<4);
            size_t ga = (size_t)t*NS + kb*64 + col;
            CPA16(sb + 131072 + so, (const char*)(vth + ga));
            CPA16(sb + 163840 + so, (const char*)(vtl + ga));
        }
        CPA_COMMIT();
        CPA_WAIT(1);          // K_kb arrived (groups retire in order)
        __syncthreads();

        // phase 1: S = Q K^T
        float sacc[4][4];
        #pragma unroll
        for (int a = 0; a < 4; a++)
            #pragma unroll
            for (int c = 0; c < 4; c++) sacc[a][c] = 0.f;
        #pragma unroll
        for (int ks = 0; ks < 16; ks++){
            u32 a_h[4], a_l[4], b_h[2][4], b_l[2][4];
            int arow = 16*wm + (lane & 15);
            u32 ach = (u32)(ks*2 + (lane >> 4));
            u32 offA = (u32)arow*512 + ((ach ^ (u32)(arow&7))<<4);
            LDMX4(a_h, sb + offA);
            LDMX4(a_l, sb + 32768 + offA);
            #pragma unroll
            for (int p = 0; p < 2; p++){
                int brow = 32*wn + 16*p + 8*(lane >> 4) + (lane & 7);
                u32 bch = (u32)(ks*2 + ((lane >> 3) & 1));
                u32 offB = (u32)brow*512 + ((bch ^ (u32)(brow&7))<<4);
                LDMX4(b_h[p], sb + 65536 + offB);
                LDMX4(b_l[p], sb + 98304 + offB);
            }
            #pragma unroll
            for (int nt = 0; nt < 4; nt++){
                const u32* ph = &b_h[nt >> 1][(nt & 1)*2];
                const u32* pl = &b_l[nt >> 1][(nt & 1)*2];
                MMA(sacc[nt], a_h, ph[0], ph[1]);
                MMA(sacc[nt], a_h, pl[0], pl[1]);
                MMA(sacc[nt], a_l, ph[0], ph[1]);
            }
        }

        // softmax (no shift) + P store (swizzled)
        {
            int r0 = 16*wm + g;
            int r1 = r0 + 8;
            #pragma unroll
            for (int nt = 0; nt < 4; nt++){
                float p0 = __expf(sacc[nt][0]*0.0625f);
                float p1 = __expf(sacc[nt][1]*0.0625f);
                float p2 = __expf(sacc[nt][2]*0.0625f);
                float p3 = __expf(sacc[nt][3]*0.0625f);
                lacc0 += p0 + p1; lacc1 += p2 + p3;
                int col = 32*wn + 8*nt + 2*tg;
                __nv_bfloat16 h0,l0,h1,l1,h2,l2,h3,l3;
                split2(p0,h0,l0); split2(p1,h1,l1); split2(p2,h2,l2); split2(p3,h3,l3);
                u32 o0 = (u32)r0*128 + (u32)((((col>>3)) ^ (r0&7))<<4) + (u32)(col&7)*2;
                u32 o1 = (u32)r1*128 + (u32)((((col>>3)) ^ (r1&7))<<4) + (u32)(col&7)*2;
                *(__nv_bfloat162*)(sm + 196608 + o0) = __halves2bfloat162(h0,h1);
                *(__nv_bfloat162*)(sm + 204800 + o0) = __halves2bfloat162(l0,l1);
                *(__nv_bfloat162*)(sm + 196608 + o1) = __halves2bfloat162(h2,h3);
                *(__nv_bfloat162*)(sm + 204800 + o1) = __halves2bfloat162(l2,l3);
            }
        }
        CPA_WAIT(0);          // V_kb arrived
        __syncthreads();      // phase1 K reads done; P, V visible

        // issue K_{kb+1} (overlaps phase2)
        if (kb < 15){
            #pragma unroll
            for (int cc = 0; cc < 8; cc++){
                int col = kcb + cc*8;
                u32 so = (u32)krow*512 + (u32)(((col>>3) ^ (krow&7))<<4);
                size_t ga = (size_t)((kb+1)*64 + krow)*ND + col;
                CPA16(sb + 65536 + so, (const char*)(kh + ga));
                CPA16(sb + 98304 + so, (const char*)(kl + ga));
            }
            CPA_COMMIT();
        }

        // phase 2: O += P V^T
        #pragma unroll
        for (int ks = 0; ks < 4; ks++){
            u32 a_h[4], a_l[4];
            int arow = 16*wm + (lane & 15);
            u32 ach = (u32)(ks*2 + (lane >> 4));
            u32 offA = (u32)arow*128 + ((ach ^ (u32)(arow&7))<<4);
            LDMX4(a_h, sb + 196608 + offA);
            LDMX4(a_l, sb + 204800 + offA);
            #pragma unroll
            for (int p = 0; p < 8; p++){
                u32 b_h[4], b_l[4];
                int brow = 128*wn + 16*p + 8*(lane >> 4) + (lane & 7);
                u32 bch = (u32)(ks*2 + ((lane >> 3) & 1));
                u32 offB = (u32)brow*128 + ((bch ^ (u32)(brow&7))<<4);
                LDMX4(b_h, sb + 131072 + offB);
                LDMX4(b_l, sb + 163840 + offB);
                MMA(oacc[2*p],   a_h, b_h[0], b_h[1]);
                MMA(oacc[2*p],   a_h, b_l[0], b_l[1]);
                MMA(oacc[2*p],   a_l, b_h[0], b_h[1]);
                MMA(oacc[2*p+1], a_h, b_h[2], b_h[3]);
                MMA(oacc[2*p+1], a_h, b_l[2], b_l[3]);
                MMA(oacc[2*p+1], a_l, b_h[2], b_h[3]);
            }
        }
        __syncthreads();      // phase2 V/P reads done before next overwrite
    }

    // deterministic rowsum: reduce over tg lanes, then across wn warps
    lacc0 += __shfl_xor_sync(0xFFFFFFFFu, lacc0, 1);
    lacc0 += __shfl_xor_sync(0xFFFFFFFFu, lacc0, 2);
    lacc1 += __shfl_xor_sync(0xFFFFFFFFu, lacc1, 1);
    lacc1 += __shfl_xor_sync(0xFFFFFFFFu, lacc1, 2);
    if (tg == 0){
        lsum[wn*64 + 16*wm + g]     = lacc0;
        lsum[wn*64 + 16*wm + g + 8] = lacc1;
    }
    __syncthreads();

    const int r0 = 16*wm + g, r1 = r0 + 8;
    const float li0 = 1.0f / (lsum[r0] + lsum[64 + r0]);
    const float li1 = 1.0f / (lsum[r1] + lsum[64 + r1]);
    const int b = bh >> 3, h = bh & 7;
    const size_t gr0 = (size_t)(b*NS + qb*64 + r0)*NDH + (size_t)h*ND;
    const size_t gr1 = (size_t)(b*NS + qb*64 + r1)*NDH + (size_t)h*ND;
    #pragma unroll
    for (int nt = 0; nt < 16; nt++){
        int e = 128*wn + 8*nt + 2*tg;
        __nv_bfloat16 h0,l0,h1,l1,h2,l2,h3,l3;
        split2(oacc[nt][0]*li0, h0,l0); split2(oacc[nt][1]*li0, h1,l1);
        split2(oacc[nt][2]*li1, h2,l2); split2(oacc[nt][3]*li1, h3,l3);
        *(__nv_bfloat162*)(g_aoh + gr0 + e) = __halves2bfloat162(h0,h1);
        *(__nv_bfloat162*)(g_aol + gr0 + e) = __halves2bfloat162(l0,l1);
        *(__nv_bfloat162*)(g_aoh + gr1 + e) = __halves2bfloat162(h2,h3);
        *(__nv_bfloat162*)(g_aol + gr1 + e) = __halves2bfloat162(l2,l3);
    }
}

// ---------------- out projection: init + split-K ----------------
__global__ __launch_bounds__(256)
void outinit(const float* __restrict__ bo, float* __restrict__ out)
{
    int i4 = blockIdx.x*256 + threadIdx.x;
    float4 b = *(const float4*)(bo + ((i4*4) & 255));
    *(float4*)(out + (size_t)i4*4) = b;
}

__global__ __launch_bounds__(256)
void outproj(float* __restrict__ out)
{
    extern __shared__ char sm[];
    const u32 sb = smem_u32(sm);
    const int t = threadIdx.x, wid = t >> 5, lane = t & 31;
    const int g = lane >> 2, tg = lane & 3;
    const int m0 = blockIdx.y*128, n0 = blockIdx.x*128;
    const int k0 = blockIdx.z*512;
    const int wm = wid >> 2, wn = wid & 3;
    const int nc = 8;

    float acc[4][4][4];
    #pragma unroll
    for (int a = 0; a < 4; a++)
        #pragma unroll
        for (int b = 0; b < 4; b++)
            #pragma unroll
            for (int c = 0; c < 4; c++) acc[a][b][c] = 0.f;

    const int lrow = t >> 3, lc8 = (t & 7)*8;
    {
        #pragma unroll
        for (int i = 0; i < 4; i++){
            int row = lrow + 32*i;
            u32 so = (u32)(row*72 + lc8)*2;
            size_t ga = (size_t)(m0 + row)*NDH + k0 + lc8;
            size_t gb = (size_t)(n0 + row)*NDH + k0 + lc8;
            CPA16(sb + so,         (const char*)(g_aoh + ga));
            CPA16(sb + 18432 + so, (const char*)(g_aol + ga));
            CPA16(sb + 36864 + so, (const char*)(g_woth + gb));
            CPA16(sb + 55296 + so, (const char*)(g_wotl + gb));
        }
        CPA_COMMIT();
    }
    for (int c = 0; c < nc; c++){
        if (c + 1 < nc){
            u32 nb = (u32)((c+1) & 1)*73728u;
            #pragma unroll
            for (int i = 0; i < 4; i++){
                int row = lrow + 32*i;
                u32 so = nb + (u32)(row*72 + lc8)*2;
                size_t ga = (size_t)(m0 + row)*NDH + k0 + (c+1)*64 + lc8;
                size_t gb = (size_t)(n0 + row)*NDH + k0 + (c+1)*64 + lc8;
                CPA16(sb + so,         (const char*)(g_aoh + ga));
                CPA16(sb + 18432 + so, (const char*)(g_aol + ga));
                CPA16(sb + 36864 + so, (const char*)(g_woth + gb));
                CPA16(sb + 55296 + so, (const char*)(g_wotl + gb));
            }
            CPA_COMMIT();
            CPA_WAIT(1);
        } else {
            CPA_WAIT(0);
        }
        __syncthreads();
        const u32 cb = (u32)(c & 1)*73728u;
        #pragma unroll
        for (int ks = 0; ks < 4; ks++){
            u32 ah[4][4], al[4][4], bh[2][4], bl[2][4];
            #pragma unroll
            for (int mt = 0; mt < 4; mt++){
                u32 off = cb + (u32)((64*wm + 16*mt + (lane & 15))*72 + ks*16 + 8*(lane >> 4))*2;
                LDMX4(ah[mt], sb + off);
                LDMX4(al[mt], sb + 18432 + off);
            }
            #pragma unroll
            for (int p = 0; p < 2; p++){
                u32 off = cb + (u32)((32*wn + 16*p + 8*(lane >> 4) + (lane & 7))*72
                                + ks*16 + 8*((lane >> 3) & 1))*2;
                LDMX4(bh[p], sb + 36864 + off);
                LDMX4(bl[p], sb + 55296 + off);
            }
            #pragma unroll
            for (int mt = 0; mt < 4; mt++)
                #pragma unroll
                for (int nt = 0; nt < 4; nt++){
                    const u32* ph = &bh[nt >> 1][(nt & 1)*2];
                    const u32* pl = &bl[nt >> 1][(nt & 1)*2];
                    MMA(acc[mt][nt], ah[mt], ph[0], ph[1]);
                    MMA(acc[mt][nt], ah[mt], pl[0], pl[1]);
                    MMA(acc[mt][nt], al[mt], ph[0], ph[1]);
                }
        }
        __syncthreads();
    }
    #pragma unroll
    for (int mt = 0; mt < 4; mt++)
        #pragma unroll
        for (int nt = 0; nt < 4; nt++)
            #pragma unroll
            for (int hf = 0; hf < 2; hf++){
                int row = m0 + 64*wm + 16*mt + g + 8*hf;
                int col = n0 + 32*wn + 8*nt + 2*tg;
                atomicAdd(out + (size_t)row*ND + col,     acc[mt][nt][2*hf]);
                atomicAdd(out + (size_t)row*ND + col + 1, acc[mt][nt][2*hf+1]);
            }
}

extern "C" void kernel_launch(void* const* d_in, const int* in_sizes, int n_in,
                              void* d_out, int out_size)
{
    const float* Q  = (const float*)d_in[0];
    const float* K  = (const float*)d_in[1];
    const float* V  = (const float*)d_in[2];
    const float* Wq = (const float*)d_in[3];
    const float* bq = (const float*)d_in[4];
    const float* Wk = (const float*)d_in[5];
    const float* bk = (const float*)d_in[6];
    const float* Wv = (const float*)d_in[7];
    const float* bv = (const float*)d_in[8];
    const float* Wo = (const float*)d_in[9];
    const float* bo = (const float*)d_in[10];
    float* out = (float*)d_out;

    const int PROJ_SMEM = 147456;
    const int ATTN_SMEM = 213504;
    cudaFuncSetAttribute(proj<0>, cudaFuncAttributeMaxDynamicSharedMemorySize, PROJ_SMEM);
    cudaFuncSetAttribute(proj<1>, cudaFuncAttributeMaxDynamicSharedMemorySize, PROJ_SMEM);
    cudaFuncSetAttribute(outproj, cudaFuncAttributeMaxDynamicSharedMemorySize, PROJ_SMEM);
    cudaFuncSetAttribute(attn,    cudaFuncAttributeMaxDynamicSharedMemorySize, ATTN_SMEM);

    dim3 blk(256);
    splitall<<<dim3(1024, 3), blk>>>(Q, K, V);             // 0
    wtransall<<<dim3(64, 8, 4), blk>>>(Wq, Wk, Wv, Wo);    // 1
    proj<0><<<dim3(16, 32), blk, PROJ_SMEM>>>(0, 0, bq, ND, 0);   // 2
    proj<0><<<dim3(16, 32), blk, PROJ_SMEM>>>(1, 1, bk, ND, 1);   // 3
    proj<1><<<dim3(16, 32), blk, PROJ_SMEM>>>(2, 2, bv, ND, 0);   // 4
    attn<<<dim3(16, 32), blk, ATTN_SMEM>>>();                     // 5  <- ncu -s 5
    outinit<<<dim3(1024), blk>>>(bo, out);                        // 6
    outproj<<<dim3(2, 32, 4), blk, PROJ_SMEM>>>(out);             // 7
}